// round 15
// baseline (speedup 1.0000x reference)
#include <cuda_runtime.h>
#include <cuda_fp16.h>
#include <math.h>
#include <stdint.h>

#define T_TOT   16384
#define H_DIM   1024
#define I_DIM   512
#define E_NUM   8
#define TOPK    2
#define NASSIGN (T_TOT * TOPK)
#define NROWS   (NASSIGN + T_TOT)
#define KC      64
#define MAXTILES 512

typedef __half hf;

// ======================= scratch =======================
__device__ int   g_topk_idx[NASSIGN];
__device__ float g_topk_w[NASSIGN];
__device__ int   g_cnt[E_NUM];
__device__ int   g_fill[E_NUM];
__device__ int   g_tok[NASSIGN];
__device__ float g_aw[NASSIGN];
__device__ int   g_pos[NASSIGN];

// persistent-GEMM tile list
__device__ int g_tile_e[MAXTILES];
__device__ int g_tile_mb[MAXTILES];
__device__ int g_tile_off[MAXTILES];
__device__ int g_ntiles;
__device__ int g_wk0;
__device__ int g_wk1;

__device__ __align__(16) hf g_xhi[(size_t)T_TOT * H_DIM];
__device__ __align__(16) hf g_wgT[(size_t)E_NUM * I_DIM * H_DIM];
__device__ __align__(16) hf g_wuT[(size_t)E_NUM * I_DIM * H_DIM];
__device__ __align__(16) hf g_wdT[(size_t)E_NUM * H_DIM * I_DIM];
__device__ __align__(16) hf g_swgT[(size_t)I_DIM * H_DIM];
__device__ __align__(16) hf g_swuT[(size_t)I_DIM * H_DIM];
__device__ __align__(16) hf g_swdT[(size_t)H_DIM * I_DIM];
__device__ __align__(16) hf g_inter[(size_t)NROWS * I_DIM];
__device__ __align__(16) hf g_dtmp[(size_t)NROWS * H_DIM];

// ======================= helpers =======================
__device__ __forceinline__ uint32_t smem_u32(const void* p) {
    uint32_t a;
    asm("{ .reg .u64 t; cvta.to.shared.u64 t, %1; cvt.u32.u64 %0, t; }" : "=r"(a) : "l"(p));
    return a;
}
__device__ __forceinline__ void cp16(uint32_t dst, const void* src) {
    asm volatile("cp.async.cg.shared.global [%0], [%1], 16;" :: "r"(dst), "l"(src));
}
__device__ __forceinline__ void cp_commit() { asm volatile("cp.async.commit_group;" ::: "memory"); }
template <int N>
__device__ __forceinline__ void cp_wait() { asm volatile("cp.async.wait_group %0;" :: "n"(N) : "memory"); }

__device__ __forceinline__ void ldsm4(uint32_t* r, uint32_t addr) {
    asm volatile("ldmatrix.sync.aligned.m8n8.x4.shared.b16 {%0,%1,%2,%3}, [%4];"
                 : "=r"(r[0]), "=r"(r[1]), "=r"(r[2]), "=r"(r[3]) : "r"(addr));
}
__device__ __forceinline__ void mma16816(float* d, const uint32_t* a, uint32_t b0, uint32_t b1) {
    asm volatile("mma.sync.aligned.m16n8k16.row.col.f32.f16.f16.f32 "
                 "{%0,%1,%2,%3}, {%4,%5,%6,%7}, {%8,%9}, {%0,%1,%2,%3};"
                 : "+f"(d[0]), "+f"(d[1]), "+f"(d[2]), "+f"(d[3])
                 : "r"(a[0]), "r"(a[1]), "r"(a[2]), "r"(a[3]), "r"(b0), "r"(b1));
}
__device__ __forceinline__ float gelu_exact(float x) {
    return 0.5f * x * (1.0f + erff(x * 0.70710678118654752f));
}

// ======================= routing =======================
__global__ void init_kernel() {
    if (threadIdx.x < E_NUM) { g_cnt[threadIdx.x] = 0; g_fill[threadIdx.x] = 0; }
}

// 2 tokens per warp; also writes fp16(x). Accumulation order identical to prior rounds.
__global__ void __launch_bounds__(256) router_kernel(const float* __restrict__ X,
                                                     const float* __restrict__ GW) {
    __shared__ float sgw[E_NUM * H_DIM];
    for (int i = threadIdx.x; i < E_NUM * H_DIM; i += 256) sgw[i] = GW[i];
    __syncthreads();
    const int warp = threadIdx.x >> 5, lane = threadIdx.x & 31;
    const int t0 = blockIdx.x * 16 + warp * 2;
    const float* x0 = X + (size_t)t0 * H_DIM;
    hf* xo0 = g_xhi + (size_t)t0 * H_DIM;

    float acc[2][E_NUM];
#pragma unroll
    for (int k = 0; k < 2; k++)
#pragma unroll
        for (int e = 0; e < E_NUM; e++) acc[k][e] = 0.0f;

    for (int h = lane * 4; h < H_DIM; h += 128) {
        float4 v[2];
#pragma unroll
        for (int k = 0; k < 2; k++) v[k] = *(const float4*)(x0 + (size_t)k * H_DIM + h);
#pragma unroll
        for (int k = 0; k < 2; k++) {
            __half2 p0 = __floats2half2_rn(v[k].x, v[k].y);
            __half2 p1 = __floats2half2_rn(v[k].z, v[k].w);
            uint2 w = {*(uint32_t*)&p0, *(uint32_t*)&p1};
            *(uint2*)(xo0 + (size_t)k * H_DIM + h) = w;
        }
#pragma unroll
        for (int e = 0; e < E_NUM; e++) {
            const float4 g = *(const float4*)(sgw + e * H_DIM + h);
#pragma unroll
            for (int k = 0; k < 2; k++)
                acc[k][e] += v[k].x * g.x + v[k].y * g.y + v[k].z * g.z + v[k].w * g.w;
        }
    }
#pragma unroll
    for (int k = 0; k < 2; k++)
#pragma unroll
        for (int e = 0; e < E_NUM; e++)
#pragma unroll
            for (int o = 16; o > 0; o >>= 1)
                acc[k][e] += __shfl_down_sync(0xffffffffu, acc[k][e], o);

#pragma unroll
    for (int k = 0; k < 2; k++) {
        if (lane == 0) {
            const int t = t0 + k;
            float l0 = -1e30f, l1 = -1e30f;
            int i0 = 0, i1 = 0;
#pragma unroll
            for (int e = 0; e < E_NUM; e++) {
                const float v = acc[k][e];
                if (v > l0)      { l1 = l0; i1 = i0; l0 = v; i0 = e; }
                else if (v > l1) { l1 = v; i1 = e; }
            }
            const float w1 = expf(l1 - l0);
            const float inv = 1.0f / (1.0f + w1);
            g_topk_idx[t * 2 + 0] = i0;
            g_topk_idx[t * 2 + 1] = i1;
            g_topk_w[t * 2 + 0] = inv;
            g_topk_w[t * 2 + 1] = w1 * inv;
            atomicAdd(&g_cnt[i0], 1);
            atomicAdd(&g_cnt[i1], 1);
        }
    }
}

// scatter with smem-aggregated atomics
__global__ void __launch_bounds__(256) scatter_kernel() {
    __shared__ int soff[E_NUM];
    __shared__ int scnt[E_NUM];
    __shared__ int sbase[E_NUM];
    const int tid = threadIdx.x;
    if (tid < E_NUM) scnt[tid] = 0;
    if (tid == 0) {
        int s = 0;
#pragma unroll
        for (int e = 0; e < E_NUM; e++) { soff[e] = s; s += g_cnt[e]; }
    }
    __syncthreads();
    const int t = blockIdx.x * 256 + tid;
    const int e0 = g_topk_idx[t * 2 + 0];
    const int e1 = g_topk_idx[t * 2 + 1];
    const int r0 = atomicAdd(&scnt[e0], 1);
    const int r1 = atomicAdd(&scnt[e1], 1);
    __syncthreads();
    if (tid < E_NUM) sbase[tid] = atomicAdd(&g_fill[tid], scnt[tid]);
    __syncthreads();
    const int p0 = soff[e0] + sbase[e0] + r0;
    const int p1 = soff[e1] + sbase[e1] + r1;
    g_tok[p0] = t;  g_aw[p0] = g_topk_w[t * 2 + 0];  g_pos[t * 2 + 0] = p0;
    g_tok[p1] = t;  g_aw[p1] = g_topk_w[t * 2 + 1];  g_pos[t * 2 + 1] = p1;
}

// build persistent-GEMM tile list: (expert, mb, row-offset) per 128-row tile; e=8 is shared
__global__ void build_tiles_kernel() {
    __shared__ int scnt[E_NUM + 1];
    __shared__ int sstart[E_NUM + 2];   // tile-index start per expert
    __shared__ int srow[E_NUM + 1];     // row offset per expert
    const int tid = threadIdx.x;
    if (tid == 0) {
        int rs = 0, ts = 0;
#pragma unroll
        for (int e = 0; e < E_NUM; e++) {
            const int c = g_cnt[e];
            scnt[e] = c;
            srow[e] = rs;
            sstart[e] = ts;
            rs += c;
            ts += (c + 127) >> 7;
        }
        scnt[E_NUM] = T_TOT;
        srow[E_NUM] = NASSIGN;
        sstart[E_NUM] = ts;
        sstart[E_NUM + 1] = ts + (T_TOT >> 7);
        g_ntiles = sstart[E_NUM + 1];
        g_wk0 = 0;
        g_wk1 = 0;
    }
    __syncthreads();
    if (tid <= E_NUM) {
        const int e = tid;
        const int nt = (scnt[e] + 127) >> 7;
        const int base = sstart[e];
        for (int i = 0; i < nt; i++) {
            g_tile_e[base + i] = e;
            g_tile_mb[base + i] = i * 128;
            g_tile_off[base + i] = srow[e];
        }
    }
}

// ======================= weight preprocessing (side stream) =======================
__global__ void __launch_bounds__(256) trans_w1_kernel(const float* __restrict__ Wg,
                                                       const float* __restrict__ Wu,
                                                       const float* __restrict__ sWg,
                                                       const float* __restrict__ sWu) {
    const int z = blockIdx.z;
    const float* src;
    hf* dst;
    if (z < 8)       { src = Wg + (size_t)z * H_DIM * I_DIM;        dst = g_wgT + (size_t)z * I_DIM * H_DIM; }
    else if (z < 16) { src = Wu + (size_t)(z - 8) * H_DIM * I_DIM;  dst = g_wuT + (size_t)(z - 8) * I_DIM * H_DIM; }
    else if (z == 16){ src = sWg;                                   dst = g_swgT; }
    else             { src = sWu;                                   dst = g_swuT; }

    __shared__ float t[32][33];
    const int c0 = blockIdx.x * 32, r0 = blockIdx.y * 32;
    const int tx = threadIdx.x & 31, ty = threadIdx.x >> 5;
#pragma unroll
    for (int j = 0; j < 32; j += 8)
        t[ty + j][tx] = src[(size_t)(r0 + ty + j) * I_DIM + c0 + tx];
    __syncthreads();
#pragma unroll
    for (int j = 0; j < 32; j += 8)
        dst[(size_t)(c0 + ty + j) * H_DIM + r0 + tx] = __float2half_rn(t[tx][ty + j]);
}

__global__ void __launch_bounds__(256) trans_w2_kernel(const float* __restrict__ Wd,
                                                       const float* __restrict__ sWd) {
    const int z = blockIdx.z;
    const float* src;
    hf* dst;
    if (z < 8) { src = Wd + (size_t)z * I_DIM * H_DIM; dst = g_wdT + (size_t)z * H_DIM * I_DIM; }
    else       { src = sWd;                            dst = g_swdT; }

    __shared__ float t[32][33];
    const int c0 = blockIdx.x * 32, r0 = blockIdx.y * 32;
    const int tx = threadIdx.x & 31, ty = threadIdx.x >> 5;
#pragma unroll
    for (int j = 0; j < 32; j += 8)
        t[ty + j][tx] = src[(size_t)(r0 + ty + j) * H_DIM + c0 + tx];
    __syncthreads();
#pragma unroll
    for (int j = 0; j < 32; j += 8)
        dst[(size_t)(c0 + ty + j) * I_DIM + r0 + tx] = __float2half_rn(t[tx][ty + j]);
}

// ======================= gate+up GEMM (persistent, 3-stage, 96KB) =======================
#define GU_AH  0u
#define GU_BG  16384u
#define GU_BU  24576u
#define GU_STAGE 32768u
#define GU_SMEM  (3 * 32768)

__global__ void __launch_bounds__(256) gu_mma_kernel(const hf* __restrict__ Wg_all,
                                                     const hf* __restrict__ Wu_all,
                                                     const hf* __restrict__ sWg,
                                                     const hf* __restrict__ sWu,
                                                     hf* __restrict__ oInter) {
    extern __shared__ char dsm[];
    __shared__ int stok[128];
    __shared__ int swk;
    const uint32_t sb = smem_u32(dsm);
    const int tid = threadIdx.x;
    const int warp = tid >> 5, lane = tid & 31;
    const int m0 = (warp & 3) * 32;
    const int n0 = (warp >> 2) * 32;
    const int hl = lane >> 4;
    const int l15 = lane & 15;
    const int cx = tid & 7;
    const int rb = tid >> 3;
    const uint32_t so = (uint32_t)rb * 128u + (uint32_t)(((cx ^ (rb & 7))) * 16);

    uint32_t aRow[2], aXor[2], bRow[2], bXor[2];
#pragma unroll
    for (int mt = 0; mt < 2; mt++) {
        const int r = m0 + mt * 16 + l15;
        aRow[mt] = (uint32_t)r * 128u;
        aXor[mt] = (uint32_t)(r & 7);
    }
#pragma unroll
    for (int p = 0; p < 2; p++) {
        const int r = n0 + p * 16 + l15;
        bRow[p] = (uint32_t)r * 128u;
        bXor[p] = (uint32_t)(r & 7);
    }

    for (;;) {
        if (tid == 0) swk = atomicAdd(&g_wk0, 1);
        __syncthreads();                       // broadcast + protect smem reuse
        const int widx = swk;
        const int tile = widx >> 3;
        if (tile >= g_ntiles) break;
        const int nx = widx & 7;

        const int e   = g_tile_e[tile];
        const int mb  = g_tile_mb[tile];
        const int off = g_tile_off[tile];
        const bool SHARED = (e == E_NUM);
        const int cnt = SHARED ? T_TOT : g_cnt[e];
        const int nb  = nx * 64;

        if (tid < 128) {
            int r = mb + tid;
            if (r >= cnt) r = cnt - 1;
            stok[tid] = SHARED ? r : g_tok[off + r];
        }
        __syncthreads();

        const hf* Bg = SHARED ? sWg : Wg_all + (size_t)e * I_DIM * H_DIM;
        const hf* Bu = SHARED ? sWu : Wu_all + (size_t)e * I_DIM * H_DIM;

        const hf *aP[4], *bgP[2], *buP[2];
#pragma unroll
        for (int j = 0; j < 4; j++)
            aP[j] = g_xhi + (size_t)stok[rb + 32 * j] * H_DIM + cx * 8;
#pragma unroll
        for (int j = 0; j < 2; j++) {
            const size_t brow = (size_t)(nb + rb + 32 * j) * H_DIM + cx * 8;
            bgP[j] = Bg + brow;
            buP[j] = Bu + brow;
        }

        float accg[2][4][4], accu[2][4][4];
#pragma unroll
        for (int mt = 0; mt < 2; mt++)
#pragma unroll
            for (int nt = 0; nt < 4; nt++)
#pragma unroll
                for (int q = 0; q < 4; q++) { accg[mt][nt][q] = 0.0f; accu[mt][nt][q] = 0.0f; }

        const int NCH = H_DIM / KC;   // 16
#pragma unroll
        for (int pc = 0; pc < 2; pc++) {
            const uint32_t d = sb + (uint32_t)pc * GU_STAGE;
            const int k0 = pc * KC;
#pragma unroll
            for (int j = 0; j < 4; j++) cp16(d + GU_AH + so + j * 4096u, aP[j] + k0);
#pragma unroll
            for (int j = 0; j < 2; j++) {
                cp16(d + GU_BG + so + j * 4096u, bgP[j] + k0);
                cp16(d + GU_BU + so + j * 4096u, buP[j] + k0);
            }
            cp_commit();
        }

        int wst = 2;
        for (int c = 0; c < NCH; c++) {
            cp_wait<1>();
            __syncthreads();
            if (c + 2 < NCH) {
                const uint32_t d = sb + (uint32_t)wst * GU_STAGE;
                const int k0 = (c + 2) * KC;
#pragma unroll
                for (int j = 0; j < 4; j++) cp16(d + GU_AH + so + j * 4096u, aP[j] + k0);
#pragma unroll
                for (int j = 0; j < 2; j++) {
                    cp16(d + GU_BG + so + j * 4096u, bgP[j] + k0);
                    cp16(d + GU_BU + so + j * 4096u, buP[j] + k0);
                }
            }
            cp_commit();

            const uint32_t st = sb + (uint32_t)((wst + 1) % 3) * GU_STAGE;
            wst = (wst + 1) % 3;
#pragma unroll
            for (int kk = 0; kk < 4; kk++) {
                const uint32_t ku = (uint32_t)(2 * kk + hl);
                uint32_t ah[2][4];
#pragma unroll
                for (int mt = 0; mt < 2; mt++)
                    ldsm4(ah[mt], st + GU_AH + aRow[mt] + ((ku ^ aXor[mt]) << 4));
                uint32_t bg[2][4], bu[2][4];
#pragma unroll
                for (int p = 0; p < 2; p++) {
                    const uint32_t bo = bRow[p] + ((ku ^ bXor[p]) << 4);
                    ldsm4(bg[p], st + GU_BG + bo);
                    ldsm4(bu[p], st + GU_BU + bo);
                }
#pragma unroll
                for (int mt = 0; mt < 2; mt++)
#pragma unroll
                    for (int p = 0; p < 2; p++)
#pragma unroll
                        for (int q = 0; q < 2; q++) {
                            const int nt = 2 * p + q;
                            mma16816(accg[mt][nt], ah[mt], bg[p][q], bg[p][q + 2]);
                            mma16816(accu[mt][nt], ah[mt], bu[p][q], bu[p][q + 2]);
                        }
            }
        }

        const int colq = (lane & 3) * 2;
#pragma unroll
        for (int mt = 0; mt < 2; mt++) {
#pragma unroll
            for (int half = 0; half < 2; half++) {
                const int gm = mb + m0 + mt * 16 + (lane >> 2) + half * 8;
                if (gm >= cnt) continue;
                const size_t orow = (size_t)(off + gm) * I_DIM;
#pragma unroll
                for (int nt = 0; nt < 4; nt++) {
                    const float g0 = accg[mt][nt][half * 2 + 0];
                    const float g1 = accg[mt][nt][half * 2 + 1];
                    const float u0 = accu[mt][nt][half * 2 + 0];
                    const float u1 = accu[mt][nt][half * 2 + 1];
                    __half2 v = __floats2half2_rn(gelu_exact(g0) * u0, gelu_exact(g1) * u1);
                    *(__half2*)(oInter + orow + nb + n0 + nt * 8 + colq) = v;
                }
            }
        }
        __syncthreads();
    }
}

// ======================= down GEMM (persistent, 3-stage, 96KB) =======================
#define DN_AH 0u
#define DN_B  16384u
#define DN_STAGE 32768u
#define DN_SMEM  (3 * 32768)

__global__ void __launch_bounds__(256) dn_mma_kernel(const hf* __restrict__ Inter,
                                                     const hf* __restrict__ Wd_all,
                                                     const hf* __restrict__ sWd,
                                                     hf* __restrict__ dtmp) {
    extern __shared__ char dsm[];
    __shared__ int swk;
    const uint32_t sb = smem_u32(dsm);
    const int tid = threadIdx.x;
    const int warp = tid >> 5, lane = tid & 31;
    const int m0 = (warp & 3) * 32;
    const int n0 = (warp >> 2) * 64;
    const int hl = lane >> 4;
    const int l15 = lane & 15;
    const int cx = tid & 7;
    const int rb = tid >> 3;
    const uint32_t so = (uint32_t)rb * 128u + (uint32_t)(((cx ^ (rb & 7))) * 16);

    uint32_t aRow[2], aXor[2], bRow[4], bXor[4];
#pragma unroll
    for (int mt = 0; mt < 2; mt++) {
        const int r = m0 + mt * 16 + l15;
        aRow[mt] = (uint32_t)r * 128u;
        aXor[mt] = (uint32_t)(r & 7);
    }
#pragma unroll
    for (int p = 0; p < 4; p++) {
        const int r = n0 + p * 16 + l15;
        bRow[p] = (uint32_t)r * 128u;
        bXor[p] = (uint32_t)(r & 7);
    }

    for (;;) {
        if (tid == 0) swk = atomicAdd(&g_wk1, 1);
        __syncthreads();
        const int widx = swk;
        const int tile = widx >> 3;
        if (tile >= g_ntiles) break;
        const int nx = widx & 7;

        const int e   = g_tile_e[tile];
        const int mb  = g_tile_mb[tile];
        const int off = g_tile_off[tile];
        const bool SHARED = (e == E_NUM);
        const int cnt = SHARED ? T_TOT : g_cnt[e];
        const int nb  = nx * 128;

        const hf* B = SHARED ? sWd : Wd_all + (size_t)e * H_DIM * I_DIM;

        const hf *aP[4], *bP[4];
#pragma unroll
        for (int j = 0; j < 4; j++) {
            int lr = mb + rb + 32 * j;
            if (lr >= cnt) lr = cnt - 1;
            aP[j] = Inter + (size_t)(off + lr) * I_DIM + cx * 8;
            bP[j] = B + (size_t)(nb + rb + 32 * j) * I_DIM + cx * 8;
        }

        float acc[2][8][4];
#pragma unroll
        for (int mt = 0; mt < 2; mt++)
#pragma unroll
            for (int nt = 0; nt < 8; nt++)
#pragma unroll
                for (int q = 0; q < 4; q++) acc[mt][nt][q] = 0.0f;

        const int NCH = I_DIM / KC;   // 8
#pragma unroll
        for (int pc = 0; pc < 2; pc++) {
            const uint32_t d = sb + (uint32_t)pc * DN_STAGE;
            const int k0 = pc * KC;
#pragma unroll
            for (int j = 0; j < 4; j++) {
                cp16(d + DN_AH + so + j * 4096u, aP[j] + k0);
                cp16(d + DN_B  + so + j * 4096u, bP[j] + k0);
            }
            cp_commit();
        }

        int wst = 2;
        for (int c = 0; c < NCH; c++) {
            cp_wait<1>();
            __syncthreads();
            if (c + 2 < NCH) {
                const uint32_t d = sb + (uint32_t)wst * DN_STAGE;
                const int k0 = (c + 2) * KC;
#pragma unroll
                for (int j = 0; j < 4; j++) {
                    cp16(d + DN_AH + so + j * 4096u, aP[j] + k0);
                    cp16(d + DN_B  + so + j * 4096u, bP[j] + k0);
                }
            }
            cp_commit();

            const uint32_t st = sb + (uint32_t)((wst + 1) % 3) * DN_STAGE;
            wst = (wst + 1) % 3;
#pragma unroll
            for (int kk = 0; kk < 4; kk++) {
                const uint32_t ku = (uint32_t)(2 * kk + hl);
                uint32_t ah[2][4];
#pragma unroll
                for (int mt = 0; mt < 2; mt++)
                    ldsm4(ah[mt], st + DN_AH + aRow[mt] + ((ku ^ aXor[mt]) << 4));
                uint32_t bh[4][4];
#pragma unroll
                for (int p = 0; p < 4; p++)
                    ldsm4(bh[p], st + DN_B + bRow[p] + ((ku ^ bXor[p]) << 4));
#pragma unroll
                for (int mt = 0; mt < 2; mt++)
#pragma unroll
                    for (int p = 0; p < 4; p++)
#pragma unroll
                        for (int q = 0; q < 2; q++) {
                            const int nt = 2 * p + q;
                            mma16816(acc[mt][nt], ah[mt], bh[p][q], bh[p][q + 2]);
                        }
            }
        }

        const int colq = (lane & 3) * 2;
#pragma unroll
        for (int mt = 0; mt < 2; mt++) {
#pragma unroll
            for (int half = 0; half < 2; half++) {
                const int gm = mb + m0 + mt * 16 + (lane >> 2) + half * 8;
                if (gm >= cnt) continue;
                const float w = SHARED ? 1.0f : g_aw[off + gm];
                hf* op = dtmp + (size_t)(off + gm) * H_DIM + nb + n0 + colq;
#pragma unroll
                for (int nt = 0; nt < 8; nt++) {
                    __half2 v = __floats2half2_rn(w * acc[mt][nt][half * 2 + 0],
                                                  w * acc[mt][nt][half * 2 + 1]);
                    *(__half2*)(op + nt * 8) = v;
                }
            }
        }
        __syncthreads();
    }
}

// ======================= combine =======================
__global__ void __launch_bounds__(256) combine_kernel(float* __restrict__ out) {
    const int t = blockIdx.x * 2 + (threadIdx.x >> 7);
    const int c = (threadIdx.x & 127) * 8;
    const int p0 = g_pos[t * 2 + 0];
    const int p1 = g_pos[t * 2 + 1];
    const uint4 av = *(const uint4*)(g_dtmp + (size_t)p0 * H_DIM + c);
    const uint4 bv = *(const uint4*)(g_dtmp + (size_t)p1 * H_DIM + c);
    const uint4 sv = *(const uint4*)(g_dtmp + (size_t)(NASSIGN + t) * H_DIM + c);
    const uint32_t aw[4] = {av.x, av.y, av.z, av.w};
    const uint32_t bw[4] = {bv.x, bv.y, bv.z, bv.w};
    const uint32_t sw[4] = {sv.x, sv.y, sv.z, sv.w};
    float o[8];
#pragma unroll
    for (int i = 0; i < 4; i++) {
        const float2 a = __half22float2(*(const __half2*)&aw[i]);
        const float2 b = __half22float2(*(const __half2*)&bw[i]);
        const float2 s = __half22float2(*(const __half2*)&sw[i]);
        o[i * 2 + 0] = s.x + a.x + b.x;
        o[i * 2 + 1] = s.y + a.y + b.y;
    }
    float* op = out + (size_t)t * H_DIM + c;
    *(float4*)(op + 0) = make_float4(o[0], o[1], o[2], o[3]);
    *(float4*)(op + 4) = make_float4(o[4], o[5], o[6], o[7]);
}

// ======================= launch =======================
extern "C" void kernel_launch(void* const* d_in, const int* in_sizes, int n_in,
                              void* d_out, int out_size) {
    const float* X   = (const float*)d_in[0];
    const float* GW  = (const float*)d_in[1];
    const float* Wg  = (const float*)d_in[2];
    const float* Wu  = (const float*)d_in[3];
    const float* Wd  = (const float*)d_in[4];
    const float* sWg = (const float*)d_in[5];
    const float* sWu = (const float*)d_in[6];
    const float* sWd = (const float*)d_in[7];
    float* out = (float*)d_out;

    static cudaStream_t s_side = nullptr;
    static cudaEvent_t  s_evFork = nullptr, s_evJoin = nullptr;
    static int s_nsm = 148;
    if (s_side == nullptr) {
        cudaStreamCreateWithFlags(&s_side, cudaStreamNonBlocking);
        cudaEventCreateWithFlags(&s_evFork, cudaEventDisableTiming);
        cudaEventCreateWithFlags(&s_evJoin, cudaEventDisableTiming);
        cudaFuncSetAttribute(gu_mma_kernel, cudaFuncAttributeMaxDynamicSharedMemorySize, GU_SMEM);
        cudaFuncSetAttribute(dn_mma_kernel, cudaFuncAttributeMaxDynamicSharedMemorySize, DN_SMEM);
        cudaDeviceGetAttribute(&s_nsm, cudaDevAttrMultiProcessorCount, 0);
    }

    hf *wgT, *wuT, *wdT, *sgT, *suT, *sdT, *inter, *dtmp;
    cudaGetSymbolAddress((void**)&wgT, g_wgT);
    cudaGetSymbolAddress((void**)&wuT, g_wuT);
    cudaGetSymbolAddress((void**)&wdT, g_wdT);
    cudaGetSymbolAddress((void**)&sgT, g_swgT);
    cudaGetSymbolAddress((void**)&suT, g_swuT);
    cudaGetSymbolAddress((void**)&sdT, g_swdT);
    cudaGetSymbolAddress((void**)&inter, g_inter);
    cudaGetSymbolAddress((void**)&dtmp, g_dtmp);

    // fork: weight preprocessing on side stream (hides under latency-bound routing chain)
    cudaEventRecord(s_evFork, (cudaStream_t)0);
    cudaStreamWaitEvent(s_side, s_evFork, 0);
    trans_w1_kernel<<<dim3(I_DIM / 32, H_DIM / 32, 18), 256, 0, s_side>>>(Wg, Wu, sWg, sWu);
    trans_w2_kernel<<<dim3(H_DIM / 32, I_DIM / 32, 9), 256, 0, s_side>>>(Wd, sWd);
    cudaEventRecord(s_evJoin, s_side);

    // routing chain on main stream (router also writes fp16(x))
    init_kernel<<<1, 32>>>();
    router_kernel<<<T_TOT / 16, 256>>>(X, GW);
    scatter_kernel<<<T_TOT / 256, 256>>>();
    build_tiles_kernel<<<1, 32>>>();

    // join
    cudaStreamWaitEvent((cudaStream_t)0, s_evJoin, 0);

    // persistent GEMMs: exactly 2 CTAs per SM, work-stealing over tile list
    gu_mma_kernel<<<2 * s_nsm, 256, GU_SMEM>>>(wgT, wuT, sgT, suT, inter);
    dn_mma_kernel<<<2 * s_nsm, 256, DN_SMEM>>>(inter, wdT, sdT, dtmp);
    combine_kernel<<<T_TOT / 2, 256>>>(out);
}

// round 16
// speedup vs baseline: 1.1745x; 1.1745x over previous
#include <cuda_runtime.h>
#include <cuda_fp16.h>
#include <math.h>
#include <stdint.h>

#define T_TOT   16384
#define H_DIM   1024
#define I_DIM   512
#define E_NUM   8
#define TOPK    2
#define NASSIGN (T_TOT * TOPK)
#define NROWS   (NASSIGN + T_TOT)
#define KC      64

typedef __half hf;

// ======================= scratch =======================
__device__ int   g_topk_idx[NASSIGN];
__device__ float g_topk_w[NASSIGN];
__device__ int   g_cnt[E_NUM];
__device__ int   g_fill[E_NUM];
__device__ int   g_tok[NASSIGN];
__device__ float g_aw[NASSIGN];
__device__ int   g_pos[NASSIGN];

__device__ __align__(16) hf g_xhi[(size_t)T_TOT * H_DIM];
__device__ __align__(16) hf g_wgT[(size_t)E_NUM * I_DIM * H_DIM];
__device__ __align__(16) hf g_wuT[(size_t)E_NUM * I_DIM * H_DIM];
__device__ __align__(16) hf g_wdT[(size_t)E_NUM * H_DIM * I_DIM];
__device__ __align__(16) hf g_swgT[(size_t)I_DIM * H_DIM];
__device__ __align__(16) hf g_swuT[(size_t)I_DIM * H_DIM];
__device__ __align__(16) hf g_swdT[(size_t)H_DIM * I_DIM];
__device__ __align__(16) hf g_inter[(size_t)NROWS * I_DIM];
__device__ __align__(16) hf g_dtmp[(size_t)NROWS * H_DIM];

// ======================= helpers =======================
__device__ __forceinline__ uint32_t smem_u32(const void* p) {
    uint32_t a;
    asm("{ .reg .u64 t; cvta.to.shared.u64 t, %1; cvt.u32.u64 %0, t; }" : "=r"(a) : "l"(p));
    return a;
}
__device__ __forceinline__ void cp16(uint32_t dst, const void* src) {
    asm volatile("cp.async.cg.shared.global [%0], [%1], 16;" :: "r"(dst), "l"(src));
}
__device__ __forceinline__ void cp_commit() { asm volatile("cp.async.commit_group;" ::: "memory"); }
template <int N>
__device__ __forceinline__ void cp_wait() { asm volatile("cp.async.wait_group %0;" :: "n"(N) : "memory"); }

__device__ __forceinline__ void ldsm4(uint32_t* r, uint32_t addr) {
    asm volatile("ldmatrix.sync.aligned.m8n8.x4.shared.b16 {%0,%1,%2,%3}, [%4];"
                 : "=r"(r[0]), "=r"(r[1]), "=r"(r[2]), "=r"(r[3]) : "r"(addr));
}
__device__ __forceinline__ void mma16816(float* d, const uint32_t* a, uint32_t b0, uint32_t b1) {
    asm volatile("mma.sync.aligned.m16n8k16.row.col.f32.f16.f16.f32 "
                 "{%0,%1,%2,%3}, {%4,%5,%6,%7}, {%8,%9}, {%0,%1,%2,%3};"
                 : "+f"(d[0]), "+f"(d[1]), "+f"(d[2]), "+f"(d[3])
                 : "r"(a[0]), "r"(a[1]), "r"(a[2]), "r"(a[3]), "r"(b0), "r"(b1));
}
__device__ __forceinline__ float gelu_exact(float x) {
    return 0.5f * x * (1.0f + erff(x * 0.70710678118654752f));
}

// ======================= routing =======================
__global__ void init_kernel() {
    if (threadIdx.x < E_NUM) { g_cnt[threadIdx.x] = 0; g_fill[threadIdx.x] = 0; }
}

// 2 tokens per warp; also writes fp16(x). min 6 CTAs/SM to lift occupancy.
__global__ void __launch_bounds__(256, 6) router_kernel(const float* __restrict__ X,
                                                        const float* __restrict__ GW) {
    __shared__ float sgw[E_NUM * H_DIM];
    for (int i = threadIdx.x; i < E_NUM * H_DIM; i += 256) sgw[i] = GW[i];
    __syncthreads();
    const int warp = threadIdx.x >> 5, lane = threadIdx.x & 31;
    const int t0 = blockIdx.x * 16 + warp * 2;
    const float* x0 = X + (size_t)t0 * H_DIM;
    hf* xo0 = g_xhi + (size_t)t0 * H_DIM;

    float acc[2][E_NUM];
#pragma unroll
    for (int k = 0; k < 2; k++)
#pragma unroll
        for (int e = 0; e < E_NUM; e++) acc[k][e] = 0.0f;

    for (int h = lane * 4; h < H_DIM; h += 128) {
        float4 v[2];
#pragma unroll
        for (int k = 0; k < 2; k++) v[k] = *(const float4*)(x0 + (size_t)k * H_DIM + h);
#pragma unroll
        for (int k = 0; k < 2; k++) {
            __half2 p0 = __floats2half2_rn(v[k].x, v[k].y);
            __half2 p1 = __floats2half2_rn(v[k].z, v[k].w);
            uint2 w = {*(uint32_t*)&p0, *(uint32_t*)&p1};
            *(uint2*)(xo0 + (size_t)k * H_DIM + h) = w;
        }
#pragma unroll
        for (int e = 0; e < E_NUM; e++) {
            const float4 g = *(const float4*)(sgw + e * H_DIM + h);
#pragma unroll
            for (int k = 0; k < 2; k++)
                acc[k][e] += v[k].x * g.x + v[k].y * g.y + v[k].z * g.z + v[k].w * g.w;
        }
    }
#pragma unroll
    for (int k = 0; k < 2; k++)
#pragma unroll
        for (int e = 0; e < E_NUM; e++)
#pragma unroll
            for (int o = 16; o > 0; o >>= 1)
                acc[k][e] += __shfl_down_sync(0xffffffffu, acc[k][e], o);

#pragma unroll
    for (int k = 0; k < 2; k++) {
        if (lane == 0) {
            const int t = t0 + k;
            float l0 = -1e30f, l1 = -1e30f;
            int i0 = 0, i1 = 0;
#pragma unroll
            for (int e = 0; e < E_NUM; e++) {
                const float v = acc[k][e];
                if (v > l0)      { l1 = l0; i1 = i0; l0 = v; i0 = e; }
                else if (v > l1) { l1 = v; i1 = e; }
            }
            const float w1 = expf(l1 - l0);
            const float inv = 1.0f / (1.0f + w1);
            g_topk_idx[t * 2 + 0] = i0;
            g_topk_idx[t * 2 + 1] = i1;
            g_topk_w[t * 2 + 0] = inv;
            g_topk_w[t * 2 + 1] = w1 * inv;
            atomicAdd(&g_cnt[i0], 1);
            atomicAdd(&g_cnt[i1], 1);
        }
    }
}

// scatter with smem-aggregated atomics
__global__ void __launch_bounds__(256) scatter_kernel() {
    __shared__ int soff[E_NUM];
    __shared__ int scnt[E_NUM];
    __shared__ int sbase[E_NUM];
    const int tid = threadIdx.x;
    if (tid < E_NUM) scnt[tid] = 0;
    if (tid == 0) {
        int s = 0;
#pragma unroll
        for (int e = 0; e < E_NUM; e++) { soff[e] = s; s += g_cnt[e]; }
    }
    __syncthreads();
    const int t = blockIdx.x * 256 + tid;
    const int e0 = g_topk_idx[t * 2 + 0];
    const int e1 = g_topk_idx[t * 2 + 1];
    const int r0 = atomicAdd(&scnt[e0], 1);
    const int r1 = atomicAdd(&scnt[e1], 1);
    __syncthreads();
    if (tid < E_NUM) sbase[tid] = atomicAdd(&g_fill[tid], scnt[tid]);
    __syncthreads();
    const int p0 = soff[e0] + sbase[e0] + r0;
    const int p1 = soff[e1] + sbase[e1] + r1;
    g_tok[p0] = t;  g_aw[p0] = g_topk_w[t * 2 + 0];  g_pos[t * 2 + 0] = p0;
    g_tok[p1] = t;  g_aw[p1] = g_topk_w[t * 2 + 1];  g_pos[t * 2 + 1] = p1;
}

// ======================= weight preprocessing (side stream) =======================
__global__ void __launch_bounds__(256) trans_w1_kernel(const float* __restrict__ Wg,
                                                       const float* __restrict__ Wu,
                                                       const float* __restrict__ sWg,
                                                       const float* __restrict__ sWu) {
    const int z = blockIdx.z;
    const float* src;
    hf* dst;
    if (z < 8)       { src = Wg + (size_t)z * H_DIM * I_DIM;        dst = g_wgT + (size_t)z * I_DIM * H_DIM; }
    else if (z < 16) { src = Wu + (size_t)(z - 8) * H_DIM * I_DIM;  dst = g_wuT + (size_t)(z - 8) * I_DIM * H_DIM; }
    else if (z == 16){ src = sWg;                                   dst = g_swgT; }
    else             { src = sWu;                                   dst = g_swuT; }

    __shared__ float t[32][33];
    const int c0 = blockIdx.x * 32, r0 = blockIdx.y * 32;
    const int tx = threadIdx.x & 31, ty = threadIdx.x >> 5;
#pragma unroll
    for (int j = 0; j < 32; j += 8)
        t[ty + j][tx] = src[(size_t)(r0 + ty + j) * I_DIM + c0 + tx];
    __syncthreads();
#pragma unroll
    for (int j = 0; j < 32; j += 8)
        dst[(size_t)(c0 + ty + j) * H_DIM + r0 + tx] = __float2half_rn(t[tx][ty + j]);
}

__global__ void __launch_bounds__(256) trans_w2_kernel(const float* __restrict__ Wd,
                                                       const float* __restrict__ sWd) {
    const int z = blockIdx.z;
    const float* src;
    hf* dst;
    if (z < 8) { src = Wd + (size_t)z * I_DIM * H_DIM; dst = g_wdT + (size_t)z * H_DIM * I_DIM; }
    else       { src = sWd;                            dst = g_swdT; }

    __shared__ float t[32][33];
    const int c0 = blockIdx.x * 32, r0 = blockIdx.y * 32;
    const int tx = threadIdx.x & 31, ty = threadIdx.x >> 5;
#pragma unroll
    for (int j = 0; j < 32; j += 8)
        t[ty + j][tx] = src[(size_t)(r0 + ty + j) * H_DIM + c0 + tx];
    __syncthreads();
#pragma unroll
    for (int j = 0; j < 32; j += 8)
        dst[(size_t)(c0 + ty + j) * I_DIM + r0 + tx] = __float2half_rn(t[tx][ty + j]);
}

__device__ __forceinline__ int expert_off(int e) {
    int s = 0;
#pragma unroll
    for (int i = 0; i < E_NUM; i++) {
        const int c = g_cnt[i];
        if (i < e) s += c;
    }
    return s;
}

// ======================= gate+up GEMM (3-stage, 96KB, z=0..7 routed, z=8 shared) ==========
#define GU_AH  0u
#define GU_BG  16384u
#define GU_BU  24576u
#define GU_STAGE 32768u
#define GU_SMEM  (3 * 32768)

__global__ void __launch_bounds__(256) gu_mma_kernel(const hf* __restrict__ Wg_all,
                                                     const hf* __restrict__ Wu_all,
                                                     const hf* __restrict__ sWg,
                                                     const hf* __restrict__ sWu,
                                                     hf* __restrict__ oInter) {
    const int e      = blockIdx.z;
    const bool SHARED = (e == E_NUM);
    const int cnt = SHARED ? T_TOT : g_cnt[e];
    const int mb  = blockIdx.y * 128;
    if (mb >= cnt) return;
    const int off = SHARED ? NASSIGN : expert_off(e);
    const int nb  = blockIdx.x * 64;

    extern __shared__ char dsm[];
    __shared__ int stok[128];
    const uint32_t sb = smem_u32(dsm);

    const int tid = threadIdx.x;
    if (tid < 128) {
        int r = mb + tid;
        if (r >= cnt) r = cnt - 1;
        stok[tid] = SHARED ? r : g_tok[off + r];
    }
    __syncthreads();

    const int cx = tid & 7;
    const int rb = tid >> 3;
    const uint32_t so = (uint32_t)rb * 128u + (uint32_t)(((cx ^ (rb & 7))) * 16);
    const hf* Bg = SHARED ? sWg : Wg_all + (size_t)e * I_DIM * H_DIM;
    const hf* Bu = SHARED ? sWu : Wu_all + (size_t)e * I_DIM * H_DIM;

    const hf *aP[4], *bgP[2], *buP[2];
#pragma unroll
    for (int j = 0; j < 4; j++)
        aP[j] = g_xhi + (size_t)stok[rb + 32 * j] * H_DIM + cx * 8;
#pragma unroll
    for (int j = 0; j < 2; j++) {
        const size_t brow = (size_t)(nb + rb + 32 * j) * H_DIM + cx * 8;
        bgP[j] = Bg + brow;
        buP[j] = Bu + brow;
    }

    const int warp = tid >> 5, lane = tid & 31;
    const int m0 = (warp & 3) * 32;
    const int n0 = (warp >> 2) * 32;
    const int hl = lane >> 4;
    const int l15 = lane & 15;

    uint32_t aRow[2], aXor[2], bRow[2], bXor[2];
#pragma unroll
    for (int mt = 0; mt < 2; mt++) {
        const int r = m0 + mt * 16 + l15;
        aRow[mt] = (uint32_t)r * 128u;
        aXor[mt] = (uint32_t)(r & 7);
    }
#pragma unroll
    for (int p = 0; p < 2; p++) {
        const int r = n0 + p * 16 + l15;
        bRow[p] = (uint32_t)r * 128u;
        bXor[p] = (uint32_t)(r & 7);
    }

    float accg[2][4][4], accu[2][4][4];
#pragma unroll
    for (int mt = 0; mt < 2; mt++)
#pragma unroll
        for (int nt = 0; nt < 4; nt++)
#pragma unroll
            for (int q = 0; q < 4; q++) { accg[mt][nt][q] = 0.0f; accu[mt][nt][q] = 0.0f; }

    const int NCH = H_DIM / KC;   // 16
#pragma unroll
    for (int pc = 0; pc < 2; pc++) {
        const uint32_t d = sb + (uint32_t)pc * GU_STAGE;
        const int k0 = pc * KC;
#pragma unroll
        for (int j = 0; j < 4; j++) cp16(d + GU_AH + so + j * 4096u, aP[j] + k0);
#pragma unroll
        for (int j = 0; j < 2; j++) {
            cp16(d + GU_BG + so + j * 4096u, bgP[j] + k0);
            cp16(d + GU_BU + so + j * 4096u, buP[j] + k0);
        }
        cp_commit();
    }

    int wst = 2;
    for (int c = 0; c < NCH; c++) {
        cp_wait<1>();
        __syncthreads();
        if (c + 2 < NCH) {
            const uint32_t d = sb + (uint32_t)wst * GU_STAGE;
            const int k0 = (c + 2) * KC;
#pragma unroll
            for (int j = 0; j < 4; j++) cp16(d + GU_AH + so + j * 4096u, aP[j] + k0);
#pragma unroll
            for (int j = 0; j < 2; j++) {
                cp16(d + GU_BG + so + j * 4096u, bgP[j] + k0);
                cp16(d + GU_BU + so + j * 4096u, buP[j] + k0);
            }
        }
        cp_commit();

        const uint32_t st = sb + (uint32_t)((wst + 1) % 3) * GU_STAGE;
        wst = (wst + 1) % 3;
#pragma unroll
        for (int kk = 0; kk < 4; kk++) {
            const uint32_t ku = (uint32_t)(2 * kk + hl);
            uint32_t ah[2][4];
#pragma unroll
            for (int mt = 0; mt < 2; mt++)
                ldsm4(ah[mt], st + GU_AH + aRow[mt] + ((ku ^ aXor[mt]) << 4));
            uint32_t bg[2][4], bu[2][4];
#pragma unroll
            for (int p = 0; p < 2; p++) {
                const uint32_t bo = bRow[p] + ((ku ^ bXor[p]) << 4);
                ldsm4(bg[p], st + GU_BG + bo);
                ldsm4(bu[p], st + GU_BU + bo);
            }
#pragma unroll
            for (int mt = 0; mt < 2; mt++)
#pragma unroll
                for (int p = 0; p < 2; p++)
#pragma unroll
                    for (int q = 0; q < 2; q++) {
                        const int nt = 2 * p + q;
                        mma16816(accg[mt][nt], ah[mt], bg[p][q], bg[p][q + 2]);
                        mma16816(accu[mt][nt], ah[mt], bu[p][q], bu[p][q + 2]);
                    }
        }
    }

    const int colq = (lane & 3) * 2;
#pragma unroll
    for (int mt = 0; mt < 2; mt++) {
#pragma unroll
        for (int half = 0; half < 2; half++) {
            const int gm = mb + m0 + mt * 16 + (lane >> 2) + half * 8;
            if (gm >= cnt) continue;
            const size_t orow = (size_t)(off + gm) * I_DIM;
#pragma unroll
            for (int nt = 0; nt < 4; nt++) {
                const float g0 = accg[mt][nt][half * 2 + 0];
                const float g1 = accg[mt][nt][half * 2 + 1];
                const float u0 = accu[mt][nt][half * 2 + 0];
                const float u1 = accu[mt][nt][half * 2 + 1];
                __half2 v = __floats2half2_rn(gelu_exact(g0) * u0, gelu_exact(g1) * u1);
                *(__half2*)(oInter + orow + nb + n0 + nt * 8 + colq) = v;
            }
        }
    }
}

// ======================= down GEMM (3-stage, 96KB, z=0..7 routed, z=8 shared) ============
#define DN_AH 0u
#define DN_B  16384u
#define DN_STAGE 32768u
#define DN_SMEM  (3 * 32768)

__global__ void __launch_bounds__(256) dn_mma_kernel(const hf* __restrict__ Inter,
                                                     const hf* __restrict__ Wd_all,
                                                     const hf* __restrict__ sWd,
                                                     hf* __restrict__ dtmp) {
    const int e      = blockIdx.z;
    const bool SHARED = (e == E_NUM);
    const int cnt = SHARED ? T_TOT : g_cnt[e];
    const int mb  = blockIdx.y * 128;
    if (mb >= cnt) return;
    const int off = SHARED ? NASSIGN : expert_off(e);
    const int nb  = blockIdx.x * 128;

    extern __shared__ char dsm[];
    const uint32_t sb = smem_u32(dsm);
    const int tid = threadIdx.x;

    const int cx = tid & 7;
    const int rb = tid >> 3;
    const uint32_t so = (uint32_t)rb * 128u + (uint32_t)(((cx ^ (rb & 7))) * 16);
    const hf* B = SHARED ? sWd : Wd_all + (size_t)e * H_DIM * I_DIM;

    const hf *aP[4], *bP[4];
#pragma unroll
    for (int j = 0; j < 4; j++) {
        int lr = mb + rb + 32 * j;
        if (lr >= cnt) lr = cnt - 1;
        aP[j] = Inter + (size_t)(off + lr) * I_DIM + cx * 8;
        bP[j] = B + (size_t)(nb + rb + 32 * j) * I_DIM + cx * 8;
    }

    const int warp = tid >> 5, lane = tid & 31;
    const int m0 = (warp & 3) * 32;
    const int n0 = (warp >> 2) * 64;
    const int hl = lane >> 4;
    const int l15 = lane & 15;

    uint32_t aRow[2], aXor[2], bRow[4], bXor[4];
#pragma unroll
    for (int mt = 0; mt < 2; mt++) {
        const int r = m0 + mt * 16 + l15;
        aRow[mt] = (uint32_t)r * 128u;
        aXor[mt] = (uint32_t)(r & 7);
    }
#pragma unroll
    for (int p = 0; p < 4; p++) {
        const int r = n0 + p * 16 + l15;
        bRow[p] = (uint32_t)r * 128u;
        bXor[p] = (uint32_t)(r & 7);
    }

    float acc[2][8][4];
#pragma unroll
    for (int mt = 0; mt < 2; mt++)
#pragma unroll
        for (int nt = 0; nt < 8; nt++)
#pragma unroll
            for (int q = 0; q < 4; q++) acc[mt][nt][q] = 0.0f;

    const int NCH = I_DIM / KC;   // 8
#pragma unroll
    for (int pc = 0; pc < 2; pc++) {
        const uint32_t d = sb + (uint32_t)pc * DN_STAGE;
        const int k0 = pc * KC;
#pragma unroll
        for (int j = 0; j < 4; j++) {
            cp16(d + DN_AH + so + j * 4096u, aP[j] + k0);
            cp16(d + DN_B  + so + j * 4096u, bP[j] + k0);
        }
        cp_commit();
    }

    int wst = 2;
    for (int c = 0; c < NCH; c++) {
        cp_wait<1>();
        __syncthreads();
        if (c + 2 < NCH) {
            const uint32_t d = sb + (uint32_t)wst * DN_STAGE;
            const int k0 = (c + 2) * KC;
#pragma unroll
            for (int j = 0; j < 4; j++) {
                cp16(d + DN_AH + so + j * 4096u, aP[j] + k0);
                cp16(d + DN_B  + so + j * 4096u, bP[j] + k0);
            }
        }
        cp_commit();

        const uint32_t st = sb + (uint32_t)((wst + 1) % 3) * DN_STAGE;
        wst = (wst + 1) % 3;
#pragma unroll
        for (int kk = 0; kk < 4; kk++) {
            const uint32_t ku = (uint32_t)(2 * kk + hl);
            uint32_t ah[2][4];
#pragma unroll
            for (int mt = 0; mt < 2; mt++)
                ldsm4(ah[mt], st + DN_AH + aRow[mt] + ((ku ^ aXor[mt]) << 4));
            uint32_t bh[4][4];
#pragma unroll
            for (int p = 0; p < 4; p++)
                ldsm4(bh[p], st + DN_B + bRow[p] + ((ku ^ bXor[p]) << 4));
#pragma unroll
            for (int mt = 0; mt < 2; mt++)
#pragma unroll
                for (int p = 0; p < 4; p++)
#pragma unroll
                    for (int q = 0; q < 2; q++) {
                        const int nt = 2 * p + q;
                        mma16816(acc[mt][nt], ah[mt], bh[p][q], bh[p][q + 2]);
                    }
        }
    }

    const int colq = (lane & 3) * 2;
#pragma unroll
    for (int mt = 0; mt < 2; mt++) {
#pragma unroll
        for (int half = 0; half < 2; half++) {
            const int gm = mb + m0 + mt * 16 + (lane >> 2) + half * 8;
            if (gm >= cnt) continue;
            const float w = SHARED ? 1.0f : g_aw[off + gm];
            hf* op = dtmp + (size_t)(off + gm) * H_DIM + nb + n0 + colq;
#pragma unroll
            for (int nt = 0; nt < 8; nt++) {
                __half2 v = __floats2half2_rn(w * acc[mt][nt][half * 2 + 0],
                                              w * acc[mt][nt][half * 2 + 1]);
                *(__half2*)(op + nt * 8) = v;
            }
        }
    }
}

// ======================= combine =======================
__global__ void __launch_bounds__(256) combine_kernel(float* __restrict__ out) {
    const int t = blockIdx.x * 2 + (threadIdx.x >> 7);
    const int c = (threadIdx.x & 127) * 8;
    const int p0 = g_pos[t * 2 + 0];
    const int p1 = g_pos[t * 2 + 1];
    const uint4 av = *(const uint4*)(g_dtmp + (size_t)p0 * H_DIM + c);
    const uint4 bv = *(const uint4*)(g_dtmp + (size_t)p1 * H_DIM + c);
    const uint4 sv = *(const uint4*)(g_dtmp + (size_t)(NASSIGN + t) * H_DIM + c);
    const uint32_t aw[4] = {av.x, av.y, av.z, av.w};
    const uint32_t bw[4] = {bv.x, bv.y, bv.z, bv.w};
    const uint32_t sw[4] = {sv.x, sv.y, sv.z, sv.w};
    float o[8];
#pragma unroll
    for (int i = 0; i < 4; i++) {
        const float2 a = __half22float2(*(const __half2*)&aw[i]);
        const float2 b = __half22float2(*(const __half2*)&bw[i]);
        const float2 s = __half22float2(*(const __half2*)&sw[i]);
        o[i * 2 + 0] = s.x + a.x + b.x;
        o[i * 2 + 1] = s.y + a.y + b.y;
    }
    float* op = out + (size_t)t * H_DIM + c;
    *(float4*)(op + 0) = make_float4(o[0], o[1], o[2], o[3]);
    *(float4*)(op + 4) = make_float4(o[4], o[5], o[6], o[7]);
}

// ======================= launch =======================
extern "C" void kernel_launch(void* const* d_in, const int* in_sizes, int n_in,
                              void* d_out, int out_size) {
    const float* X   = (const float*)d_in[0];
    const float* GW  = (const float*)d_in[1];
    const float* Wg  = (const float*)d_in[2];
    const float* Wu  = (const float*)d_in[3];
    const float* Wd  = (const float*)d_in[4];
    const float* sWg = (const float*)d_in[5];
    const float* sWu = (const float*)d_in[6];
    const float* sWd = (const float*)d_in[7];
    float* out = (float*)d_out;

    static cudaStream_t s_side = nullptr;
    static cudaEvent_t  s_evFork = nullptr, s_evJoin = nullptr;
    if (s_side == nullptr) {
        cudaStreamCreateWithFlags(&s_side, cudaStreamNonBlocking);
        cudaEventCreateWithFlags(&s_evFork, cudaEventDisableTiming);
        cudaEventCreateWithFlags(&s_evJoin, cudaEventDisableTiming);
        cudaFuncSetAttribute(gu_mma_kernel, cudaFuncAttributeMaxDynamicSharedMemorySize, GU_SMEM);
        cudaFuncSetAttribute(dn_mma_kernel, cudaFuncAttributeMaxDynamicSharedMemorySize, DN_SMEM);
    }

    hf *wgT, *wuT, *wdT, *sgT, *suT, *sdT, *inter, *dtmp;
    cudaGetSymbolAddress((void**)&wgT, g_wgT);
    cudaGetSymbolAddress((void**)&wuT, g_wuT);
    cudaGetSymbolAddress((void**)&wdT, g_wdT);
    cudaGetSymbolAddress((void**)&sgT, g_swgT);
    cudaGetSymbolAddress((void**)&suT, g_swuT);
    cudaGetSymbolAddress((void**)&sdT, g_swdT);
    cudaGetSymbolAddress((void**)&inter, g_inter);
    cudaGetSymbolAddress((void**)&dtmp, g_dtmp);

    // fork: weight preprocessing on side stream (hides under latency-bound routing chain)
    cudaEventRecord(s_evFork, (cudaStream_t)0);
    cudaStreamWaitEvent(s_side, s_evFork, 0);
    trans_w1_kernel<<<dim3(I_DIM / 32, H_DIM / 32, 18), 256, 0, s_side>>>(Wg, Wu, sWg, sWu);
    trans_w2_kernel<<<dim3(H_DIM / 32, I_DIM / 32, 9), 256, 0, s_side>>>(Wd, sWd);
    cudaEventRecord(s_evJoin, s_side);

    // routing chain on main stream (router also writes fp16(x))
    init_kernel<<<1, 32>>>();
    router_kernel<<<T_TOT / 16, 256>>>(X, GW);
    scatter_kernel<<<T_TOT / 256, 256>>>();

    // join
    cudaStreamWaitEvent((cudaStream_t)0, s_evJoin, 0);

    gu_mma_kernel<<<dim3(I_DIM / 64, T_TOT / 128, E_NUM + 1), 256, GU_SMEM>>>(
        wgT, wuT, sgT, suT, inter);
    dn_mma_kernel<<<dim3(H_DIM / 128, T_TOT / 128, E_NUM + 1), 256, DN_SMEM>>>(
        inter, wdT, sdT, dtmp);
    combine_kernel<<<T_TOT / 2, 256>>>(out);
}

// round 17
// speedup vs baseline: 1.1979x; 1.0198x over previous
#include <cuda_runtime.h>
#include <cuda_fp16.h>
#include <math.h>
#include <stdint.h>

#define T_TOT   16384
#define H_DIM   1024
#define I_DIM   512
#define E_NUM   8
#define TOPK    2
#define NASSIGN (T_TOT * TOPK)
#define NROWS   (NASSIGN + T_TOT)
#define KC      64

typedef __half hf;

// ======================= scratch =======================
__device__ int   g_topk_idx[NASSIGN];
__device__ float g_topk_w[NASSIGN];
__device__ int   g_cnt[E_NUM];
__device__ int   g_fill[E_NUM];
__device__ int   g_tok[NASSIGN];
__device__ float g_aw[NASSIGN];
__device__ int   g_pos[NASSIGN];

__device__ __align__(16) hf g_xhi[(size_t)T_TOT * H_DIM];
__device__ __align__(16) hf g_wgT[(size_t)E_NUM * I_DIM * H_DIM];
__device__ __align__(16) hf g_wuT[(size_t)E_NUM * I_DIM * H_DIM];
__device__ __align__(16) hf g_wdT[(size_t)E_NUM * H_DIM * I_DIM];
__device__ __align__(16) hf g_swgT[(size_t)I_DIM * H_DIM];
__device__ __align__(16) hf g_swuT[(size_t)I_DIM * H_DIM];
__device__ __align__(16) hf g_swdT[(size_t)H_DIM * I_DIM];
__device__ __align__(16) hf g_inter[(size_t)NROWS * I_DIM];
__device__ __align__(16) hf g_dtmp[(size_t)NROWS * H_DIM];

// ======================= helpers =======================
__device__ __forceinline__ uint32_t smem_u32(const void* p) {
    uint32_t a;
    asm("{ .reg .u64 t; cvta.to.shared.u64 t, %1; cvt.u32.u64 %0, t; }" : "=r"(a) : "l"(p));
    return a;
}
__device__ __forceinline__ void cp16(uint32_t dst, const void* src) {
    asm volatile("cp.async.cg.shared.global [%0], [%1], 16;" :: "r"(dst), "l"(src));
}
__device__ __forceinline__ void cp_commit() { asm volatile("cp.async.commit_group;" ::: "memory"); }
template <int N>
__device__ __forceinline__ void cp_wait() { asm volatile("cp.async.wait_group %0;" :: "n"(N) : "memory"); }

__device__ __forceinline__ void ldsm4(uint32_t* r, uint32_t addr) {
    asm volatile("ldmatrix.sync.aligned.m8n8.x4.shared.b16 {%0,%1,%2,%3}, [%4];"
                 : "=r"(r[0]), "=r"(r[1]), "=r"(r[2]), "=r"(r[3]) : "r"(addr));
}
__device__ __forceinline__ void mma16816(float* d, const uint32_t* a, uint32_t b0, uint32_t b1) {
    asm volatile("mma.sync.aligned.m16n8k16.row.col.f32.f16.f16.f32 "
                 "{%0,%1,%2,%3}, {%4,%5,%6,%7}, {%8,%9}, {%0,%1,%2,%3};"
                 : "+f"(d[0]), "+f"(d[1]), "+f"(d[2]), "+f"(d[3])
                 : "r"(a[0]), "r"(a[1]), "r"(a[2]), "r"(a[3]), "r"(b0), "r"(b1));
}
__device__ __forceinline__ float gelu_exact(float x) {
    return 0.5f * x * (1.0f + erff(x * 0.70710678118654752f));
}

// ======================= routing =======================
__global__ void init_kernel() {
    if (threadIdx.x < E_NUM) { g_cnt[threadIdx.x] = 0; g_fill[threadIdx.x] = 0; }
}

// 2 tokens per warp, h-loop unrolled x2 (4 independent LDG.128 in flight).
// Per-thread accumulation order unchanged -> logits bit-identical.
__global__ void __launch_bounds__(256) router_kernel(const float* __restrict__ X,
                                                     const float* __restrict__ GW) {
    __shared__ float sgw[E_NUM * H_DIM];
    for (int i = threadIdx.x; i < E_NUM * H_DIM; i += 256) sgw[i] = GW[i];
    __syncthreads();
    const int warp = threadIdx.x >> 5, lane = threadIdx.x & 31;
    const int t0 = blockIdx.x * 16 + warp * 2;
    const float* x0 = X + (size_t)t0 * H_DIM;
    hf* xo0 = g_xhi + (size_t)t0 * H_DIM;

    float acc[2][E_NUM];
#pragma unroll
    for (int k = 0; k < 2; k++)
#pragma unroll
        for (int e = 0; e < E_NUM; e++) acc[k][e] = 0.0f;

    for (int h = lane * 4; h < H_DIM; h += 256) {
        const int h1 = h + 128;
        float4 v[2], w2[2];
#pragma unroll
        for (int k = 0; k < 2; k++) {
            v[k]  = *(const float4*)(x0 + (size_t)k * H_DIM + h);
            w2[k] = *(const float4*)(x0 + (size_t)k * H_DIM + h1);
        }
#pragma unroll
        for (int k = 0; k < 2; k++) {
            __half2 p0 = __floats2half2_rn(v[k].x, v[k].y);
            __half2 p1 = __floats2half2_rn(v[k].z, v[k].w);
            uint2 wv = {*(uint32_t*)&p0, *(uint32_t*)&p1};
            *(uint2*)(xo0 + (size_t)k * H_DIM + h) = wv;
            __half2 q0 = __floats2half2_rn(w2[k].x, w2[k].y);
            __half2 q1 = __floats2half2_rn(w2[k].z, w2[k].w);
            uint2 wv1 = {*(uint32_t*)&q0, *(uint32_t*)&q1};
            *(uint2*)(xo0 + (size_t)k * H_DIM + h1) = wv1;
        }
        // chunk at h (same order as before), then chunk at h+128
#pragma unroll
        for (int e = 0; e < E_NUM; e++) {
            const float4 g = *(const float4*)(sgw + e * H_DIM + h);
#pragma unroll
            for (int k = 0; k < 2; k++)
                acc[k][e] += v[k].x * g.x + v[k].y * g.y + v[k].z * g.z + v[k].w * g.w;
        }
#pragma unroll
        for (int e = 0; e < E_NUM; e++) {
            const float4 g = *(const float4*)(sgw + e * H_DIM + h1);
#pragma unroll
            for (int k = 0; k < 2; k++)
                acc[k][e] += w2[k].x * g.x + w2[k].y * g.y + w2[k].z * g.z + w2[k].w * g.w;
        }
    }
#pragma unroll
    for (int k = 0; k < 2; k++)
#pragma unroll
        for (int e = 0; e < E_NUM; e++)
#pragma unroll
            for (int o = 16; o > 0; o >>= 1)
                acc[k][e] += __shfl_down_sync(0xffffffffu, acc[k][e], o);

#pragma unroll
    for (int k = 0; k < 2; k++) {
        if (lane == 0) {
            const int t = t0 + k;
            float l0 = -1e30f, l1 = -1e30f;
            int i0 = 0, i1 = 0;
#pragma unroll
            for (int e = 0; e < E_NUM; e++) {
                const float v = acc[k][e];
                if (v > l0)      { l1 = l0; i1 = i0; l0 = v; i0 = e; }
                else if (v > l1) { l1 = v; i1 = e; }
            }
            const float w1 = expf(l1 - l0);
            const float inv = 1.0f / (1.0f + w1);
            g_topk_idx[t * 2 + 0] = i0;
            g_topk_idx[t * 2 + 1] = i1;
            g_topk_w[t * 2 + 0] = inv;
            g_topk_w[t * 2 + 1] = w1 * inv;
            atomicAdd(&g_cnt[i0], 1);
            atomicAdd(&g_cnt[i1], 1);
        }
    }
}

// scatter with smem-aggregated atomics
__global__ void __launch_bounds__(256) scatter_kernel() {
    __shared__ int soff[E_NUM];
    __shared__ int scnt[E_NUM];
    __shared__ int sbase[E_NUM];
    const int tid = threadIdx.x;
    if (tid < E_NUM) scnt[tid] = 0;
    if (tid == 0) {
        int s = 0;
#pragma unroll
        for (int e = 0; e < E_NUM; e++) { soff[e] = s; s += g_cnt[e]; }
    }
    __syncthreads();
    const int t = blockIdx.x * 256 + tid;
    const int e0 = g_topk_idx[t * 2 + 0];
    const int e1 = g_topk_idx[t * 2 + 1];
    const int r0 = atomicAdd(&scnt[e0], 1);
    const int r1 = atomicAdd(&scnt[e1], 1);
    __syncthreads();
    if (tid < E_NUM) sbase[tid] = atomicAdd(&g_fill[tid], scnt[tid]);
    __syncthreads();
    const int p0 = soff[e0] + sbase[e0] + r0;
    const int p1 = soff[e1] + sbase[e1] + r1;
    g_tok[p0] = t;  g_aw[p0] = g_topk_w[t * 2 + 0];  g_pos[t * 2 + 0] = p0;
    g_tok[p1] = t;  g_aw[p1] = g_topk_w[t * 2 + 1];  g_pos[t * 2 + 1] = p1;
}

// ======================= weight preprocessing (side stream) =======================
__global__ void __launch_bounds__(256) trans_w1_kernel(const float* __restrict__ Wg,
                                                       const float* __restrict__ Wu,
                                                       const float* __restrict__ sWg,
                                                       const float* __restrict__ sWu) {
    const int z = blockIdx.z;
    const float* src;
    hf* dst;
    if (z < 8)       { src = Wg + (size_t)z * H_DIM * I_DIM;        dst = g_wgT + (size_t)z * I_DIM * H_DIM; }
    else if (z < 16) { src = Wu + (size_t)(z - 8) * H_DIM * I_DIM;  dst = g_wuT + (size_t)(z - 8) * I_DIM * H_DIM; }
    else if (z == 16){ src = sWg;                                   dst = g_swgT; }
    else             { src = sWu;                                   dst = g_swuT; }

    __shared__ float t[32][33];
    const int c0 = blockIdx.x * 32, r0 = blockIdx.y * 32;
    const int tx = threadIdx.x & 31, ty = threadIdx.x >> 5;
#pragma unroll
    for (int j = 0; j < 32; j += 8)
        t[ty + j][tx] = src[(size_t)(r0 + ty + j) * I_DIM + c0 + tx];
    __syncthreads();
#pragma unroll
    for (int j = 0; j < 32; j += 8)
        dst[(size_t)(c0 + ty + j) * H_DIM + r0 + tx] = __float2half_rn(t[tx][ty + j]);
}

__global__ void __launch_bounds__(256) trans_w2_kernel(const float* __restrict__ Wd,
                                                       const float* __restrict__ sWd) {
    const int z = blockIdx.z;
    const float* src;
    hf* dst;
    if (z < 8) { src = Wd + (size_t)z * I_DIM * H_DIM; dst = g_wdT + (size_t)z * H_DIM * I_DIM; }
    else       { src = sWd;                            dst = g_swdT; }

    __shared__ float t[32][33];
    const int c0 = blockIdx.x * 32, r0 = blockIdx.y * 32;
    const int tx = threadIdx.x & 31, ty = threadIdx.x >> 5;
#pragma unroll
    for (int j = 0; j < 32; j += 8)
        t[ty + j][tx] = src[(size_t)(r0 + ty + j) * H_DIM + c0 + tx];
    __syncthreads();
#pragma unroll
    for (int j = 0; j < 32; j += 8)
        dst[(size_t)(c0 + ty + j) * I_DIM + r0 + tx] = __float2half_rn(t[tx][ty + j]);
}

__device__ __forceinline__ int expert_off(int e) {
    int s = 0;
#pragma unroll
    for (int i = 0; i < E_NUM; i++) {
        const int c = g_cnt[i];
        if (i < e) s += c;
    }
    return s;
}

// ======================= gate+up GEMM (3-stage, 96KB, z=0..7 routed, z=8 shared) ==========
#define GU_AH  0u
#define GU_BG  16384u
#define GU_BU  24576u
#define GU_STAGE 32768u
#define GU_SMEM  (3 * 32768)

__global__ void __launch_bounds__(256) gu_mma_kernel(const hf* __restrict__ Wg_all,
                                                     const hf* __restrict__ Wu_all,
                                                     const hf* __restrict__ sWg,
                                                     const hf* __restrict__ sWu,
                                                     hf* __restrict__ oInter) {
    const int e      = blockIdx.z;
    const bool SHARED = (e == E_NUM);
    const int cnt = SHARED ? T_TOT : g_cnt[e];
    const int mb  = blockIdx.y * 128;
    if (mb >= cnt) return;
    const int off = SHARED ? NASSIGN : expert_off(e);
    const int nb  = blockIdx.x * 64;

    extern __shared__ char dsm[];
    __shared__ int stok[128];
    const uint32_t sb = smem_u32(dsm);

    const int tid = threadIdx.x;
    if (tid < 128) {
        int r = mb + tid;
        if (r >= cnt) r = cnt - 1;
        stok[tid] = SHARED ? r : g_tok[off + r];
    }
    __syncthreads();

    const int cx = tid & 7;
    const int rb = tid >> 3;
    const uint32_t so = (uint32_t)rb * 128u + (uint32_t)(((cx ^ (rb & 7))) * 16);
    const hf* Bg = SHARED ? sWg : Wg_all + (size_t)e * I_DIM * H_DIM;
    const hf* Bu = SHARED ? sWu : Wu_all + (size_t)e * I_DIM * H_DIM;

    const hf *aP[4], *bgP[2], *buP[2];
#pragma unroll
    for (int j = 0; j < 4; j++)
        aP[j] = g_xhi + (size_t)stok[rb + 32 * j] * H_DIM + cx * 8;
#pragma unroll
    for (int j = 0; j < 2; j++) {
        const size_t brow = (size_t)(nb + rb + 32 * j) * H_DIM + cx * 8;
        bgP[j] = Bg + brow;
        buP[j] = Bu + brow;
    }

    const int warp = tid >> 5, lane = tid & 31;
    const int m0 = (warp & 3) * 32;
    const int n0 = (warp >> 2) * 32;
    const int hl = lane >> 4;
    const int l15 = lane & 15;

    uint32_t aRow[2], aXor[2], bRow[2], bXor[2];
#pragma unroll
    for (int mt = 0; mt < 2; mt++) {
        const int r = m0 + mt * 16 + l15;
        aRow[mt] = (uint32_t)r * 128u;
        aXor[mt] = (uint32_t)(r & 7);
    }
#pragma unroll
    for (int p = 0; p < 2; p++) {
        const int r = n0 + p * 16 + l15;
        bRow[p] = (uint32_t)r * 128u;
        bXor[p] = (uint32_t)(r & 7);
    }

    float accg[2][4][4], accu[2][4][4];
#pragma unroll
    for (int mt = 0; mt < 2; mt++)
#pragma unroll
        for (int nt = 0; nt < 4; nt++)
#pragma unroll
            for (int q = 0; q < 4; q++) { accg[mt][nt][q] = 0.0f; accu[mt][nt][q] = 0.0f; }

    const int NCH = H_DIM / KC;   // 16
#pragma unroll
    for (int pc = 0; pc < 2; pc++) {
        const uint32_t d = sb + (uint32_t)pc * GU_STAGE;
        const int k0 = pc * KC;
#pragma unroll
        for (int j = 0; j < 4; j++) cp16(d + GU_AH + so + j * 4096u, aP[j] + k0);
#pragma unroll
        for (int j = 0; j < 2; j++) {
            cp16(d + GU_BG + so + j * 4096u, bgP[j] + k0);
            cp16(d + GU_BU + so + j * 4096u, buP[j] + k0);
        }
        cp_commit();
    }

    int wst = 2;
    for (int c = 0; c < NCH; c++) {
        cp_wait<1>();
        __syncthreads();
        if (c + 2 < NCH) {
            const uint32_t d = sb + (uint32_t)wst * GU_STAGE;
            const int k0 = (c + 2) * KC;
#pragma unroll
            for (int j = 0; j < 4; j++) cp16(d + GU_AH + so + j * 4096u, aP[j] + k0);
#pragma unroll
            for (int j = 0; j < 2; j++) {
                cp16(d + GU_BG + so + j * 4096u, bgP[j] + k0);
                cp16(d + GU_BU + so + j * 4096u, buP[j] + k0);
            }
        }
        cp_commit();

        const uint32_t st = sb + (uint32_t)((wst + 1) % 3) * GU_STAGE;
        wst = (wst + 1) % 3;
#pragma unroll
        for (int kk = 0; kk < 4; kk++) {
            const uint32_t ku = (uint32_t)(2 * kk + hl);
            uint32_t ah[2][4];
#pragma unroll
            for (int mt = 0; mt < 2; mt++)
                ldsm4(ah[mt], st + GU_AH + aRow[mt] + ((ku ^ aXor[mt]) << 4));
            uint32_t bg[2][4], bu[2][4];
#pragma unroll
            for (int p = 0; p < 2; p++) {
                const uint32_t bo = bRow[p] + ((ku ^ bXor[p]) << 4);
                ldsm4(bg[p], st + GU_BG + bo);
                ldsm4(bu[p], st + GU_BU + bo);
            }
#pragma unroll
            for (int mt = 0; mt < 2; mt++)
#pragma unroll
                for (int p = 0; p < 2; p++)
#pragma unroll
                    for (int q = 0; q < 2; q++) {
                        const int nt = 2 * p + q;
                        mma16816(accg[mt][nt], ah[mt], bg[p][q], bg[p][q + 2]);
                        mma16816(accu[mt][nt], ah[mt], bu[p][q], bu[p][q + 2]);
                    }
        }
    }

    const int colq = (lane & 3) * 2;
#pragma unroll
    for (int mt = 0; mt < 2; mt++) {
#pragma unroll
        for (int half = 0; half < 2; half++) {
            const int gm = mb + m0 + mt * 16 + (lane >> 2) + half * 8;
            if (gm >= cnt) continue;
            const size_t orow = (size_t)(off + gm) * I_DIM;
#pragma unroll
            for (int nt = 0; nt < 4; nt++) {
                const float g0 = accg[mt][nt][half * 2 + 0];
                const float g1 = accg[mt][nt][half * 2 + 1];
                const float u0 = accu[mt][nt][half * 2 + 0];
                const float u1 = accu[mt][nt][half * 2 + 1];
                __half2 v = __floats2half2_rn(gelu_exact(g0) * u0, gelu_exact(g1) * u1);
                *(__half2*)(oInter + orow + nb + n0 + nt * 8 + colq) = v;
            }
        }
    }
}

// ======================= down GEMM (3-stage, 96KB, z=0..7 routed, z=8 shared) ============
#define DN_AH 0u
#define DN_B  16384u
#define DN_STAGE 32768u
#define DN_SMEM  (3 * 32768)

__global__ void __launch_bounds__(256) dn_mma_kernel(const hf* __restrict__ Inter,
                                                     const hf* __restrict__ Wd_all,
                                                     const hf* __restrict__ sWd,
                                                     hf* __restrict__ dtmp) {
    const int e      = blockIdx.z;
    const bool SHARED = (e == E_NUM);
    const int cnt = SHARED ? T_TOT : g_cnt[e];
    const int mb  = blockIdx.y * 128;
    if (mb >= cnt) return;
    const int off = SHARED ? NASSIGN : expert_off(e);
    const int nb  = blockIdx.x * 128;

    extern __shared__ char dsm[];
    const uint32_t sb = smem_u32(dsm);
    const int tid = threadIdx.x;

    const int cx = tid & 7;
    const int rb = tid >> 3;
    const uint32_t so = (uint32_t)rb * 128u + (uint32_t)(((cx ^ (rb & 7))) * 16);
    const hf* B = SHARED ? sWd : Wd_all + (size_t)e * H_DIM * I_DIM;

    const hf *aP[4], *bP[4];
#pragma unroll
    for (int j = 0; j < 4; j++) {
        int lr = mb + rb + 32 * j;
        if (lr >= cnt) lr = cnt - 1;
        aP[j] = Inter + (size_t)(off + lr) * I_DIM + cx * 8;
        bP[j] = B + (size_t)(nb + rb + 32 * j) * I_DIM + cx * 8;
    }

    const int warp = tid >> 5, lane = tid & 31;
    const int m0 = (warp & 3) * 32;
    const int n0 = (warp >> 2) * 64;
    const int hl = lane >> 4;
    const int l15 = lane & 15;

    uint32_t aRow[2], aXor[2], bRow[4], bXor[4];
#pragma unroll
    for (int mt = 0; mt < 2; mt++) {
        const int r = m0 + mt * 16 + l15;
        aRow[mt] = (uint32_t)r * 128u;
        aXor[mt] = (uint32_t)(r & 7);
    }
#pragma unroll
    for (int p = 0; p < 4; p++) {
        const int r = n0 + p * 16 + l15;
        bRow[p] = (uint32_t)r * 128u;
        bXor[p] = (uint32_t)(r & 7);
    }

    float acc[2][8][4];
#pragma unroll
    for (int mt = 0; mt < 2; mt++)
#pragma unroll
        for (int nt = 0; nt < 8; nt++)
#pragma unroll
            for (int q = 0; q < 4; q++) acc[mt][nt][q] = 0.0f;

    const int NCH = I_DIM / KC;   // 8
#pragma unroll
    for (int pc = 0; pc < 2; pc++) {
        const uint32_t d = sb + (uint32_t)pc * DN_STAGE;
        const int k0 = pc * KC;
#pragma unroll
        for (int j = 0; j < 4; j++) {
            cp16(d + DN_AH + so + j * 4096u, aP[j] + k0);
            cp16(d + DN_B  + so + j * 4096u, bP[j] + k0);
        }
        cp_commit();
    }

    int wst = 2;
    for (int c = 0; c < NCH; c++) {
        cp_wait<1>();
        __syncthreads();
        if (c + 2 < NCH) {
            const uint32_t d = sb + (uint32_t)wst * DN_STAGE;
            const int k0 = (c + 2) * KC;
#pragma unroll
            for (int j = 0; j < 4; j++) {
                cp16(d + DN_AH + so + j * 4096u, aP[j] + k0);
                cp16(d + DN_B  + so + j * 4096u, bP[j] + k0);
            }
        }
        cp_commit();

        const uint32_t st = sb + (uint32_t)((wst + 1) % 3) * DN_STAGE;
        wst = (wst + 1) % 3;
#pragma unroll
        for (int kk = 0; kk < 4; kk++) {
            const uint32_t ku = (uint32_t)(2 * kk + hl);
            uint32_t ah[2][4];
#pragma unroll
            for (int mt = 0; mt < 2; mt++)
                ldsm4(ah[mt], st + DN_AH + aRow[mt] + ((ku ^ aXor[mt]) << 4));
            uint32_t bh[4][4];
#pragma unroll
            for (int p = 0; p < 4; p++)
                ldsm4(bh[p], st + DN_B + bRow[p] + ((ku ^ bXor[p]) << 4));
#pragma unroll
            for (int mt = 0; mt < 2; mt++)
#pragma unroll
                for (int p = 0; p < 4; p++)
#pragma unroll
                    for (int q = 0; q < 2; q++) {
                        const int nt = 2 * p + q;
                        mma16816(acc[mt][nt], ah[mt], bh[p][q], bh[p][q + 2]);
                    }
        }
    }

    const int colq = (lane & 3) * 2;
#pragma unroll
    for (int mt = 0; mt < 2; mt++) {
#pragma unroll
        for (int half = 0; half < 2; half++) {
            const int gm = mb + m0 + mt * 16 + (lane >> 2) + half * 8;
            if (gm >= cnt) continue;
            const float w = SHARED ? 1.0f : g_aw[off + gm];
            hf* op = dtmp + (size_t)(off + gm) * H_DIM + nb + n0 + colq;
#pragma unroll
            for (int nt = 0; nt < 8; nt++) {
                __half2 v = __floats2half2_rn(w * acc[mt][nt][half * 2 + 0],
                                              w * acc[mt][nt][half * 2 + 1]);
                *(__half2*)(op + nt * 8) = v;
            }
        }
    }
}

// ======================= combine =======================
__global__ void __launch_bounds__(256) combine_kernel(float* __restrict__ out) {
    const int t = blockIdx.x * 2 + (threadIdx.x >> 7);
    const int c = (threadIdx.x & 127) * 8;
    const int p0 = g_pos[t * 2 + 0];
    const int p1 = g_pos[t * 2 + 1];
    const uint4 av = *(const uint4*)(g_dtmp + (size_t)p0 * H_DIM + c);
    const uint4 bv = *(const uint4*)(g_dtmp + (size_t)p1 * H_DIM + c);
    const uint4 sv = *(const uint4*)(g_dtmp + (size_t)(NASSIGN + t) * H_DIM + c);
    const uint32_t aw[4] = {av.x, av.y, av.z, av.w};
    const uint32_t bw[4] = {bv.x, bv.y, bv.z, bv.w};
    const uint32_t sw[4] = {sv.x, sv.y, sv.z, sv.w};
    float o[8];
#pragma unroll
    for (int i = 0; i < 4; i++) {
        const float2 a = __half22float2(*(const __half2*)&aw[i]);
        const float2 b = __half22float2(*(const __half2*)&bw[i]);
        const float2 s = __half22float2(*(const __half2*)&sw[i]);
        o[i * 2 + 0] = s.x + a.x + b.x;
        o[i * 2 + 1] = s.y + a.y + b.y;
    }
    float* op = out + (size_t)t * H_DIM + c;
    *(float4*)(op + 0) = make_float4(o[0], o[1], o[2], o[3]);
    *(float4*)(op + 4) = make_float4(o[4], o[5], o[6], o[7]);
}

// ======================= launch =======================
extern "C" void kernel_launch(void* const* d_in, const int* in_sizes, int n_in,
                              void* d_out, int out_size) {
    const float* X   = (const float*)d_in[0];
    const float* GW  = (const float*)d_in[1];
    const float* Wg  = (const float*)d_in[2];
    const float* Wu  = (const float*)d_in[3];
    const float* Wd  = (const float*)d_in[4];
    const float* sWg = (const float*)d_in[5];
    const float* sWu = (const float*)d_in[6];
    const float* sWd = (const float*)d_in[7];
    float* out = (float*)d_out;

    static cudaStream_t s_side = nullptr;
    static cudaEvent_t  s_evFork = nullptr, s_evJoin = nullptr;
    if (s_side == nullptr) {
        cudaStreamCreateWithFlags(&s_side, cudaStreamNonBlocking);
        cudaEventCreateWithFlags(&s_evFork, cudaEventDisableTiming);
        cudaEventCreateWithFlags(&s_evJoin, cudaEventDisableTiming);
        cudaFuncSetAttribute(gu_mma_kernel, cudaFuncAttributeMaxDynamicSharedMemorySize, GU_SMEM);
        cudaFuncSetAttribute(dn_mma_kernel, cudaFuncAttributeMaxDynamicSharedMemorySize, DN_SMEM);
    }

    hf *wgT, *wuT, *wdT, *sgT, *suT, *sdT, *inter, *dtmp;
    cudaGetSymbolAddress((void**)&wgT, g_wgT);
    cudaGetSymbolAddress((void**)&wuT, g_wuT);
    cudaGetSymbolAddress((void**)&wdT, g_wdT);
    cudaGetSymbolAddress((void**)&sgT, g_swgT);
    cudaGetSymbolAddress((void**)&suT, g_swuT);
    cudaGetSymbolAddress((void**)&sdT, g_swdT);
    cudaGetSymbolAddress((void**)&inter, g_inter);
    cudaGetSymbolAddress((void**)&dtmp, g_dtmp);

    // fork: weight preprocessing on side stream (hides under latency-bound routing chain)
    cudaEventRecord(s_evFork, (cudaStream_t)0);
    cudaStreamWaitEvent(s_side, s_evFork, 0);
    trans_w1_kernel<<<dim3(I_DIM / 32, H_DIM / 32, 18), 256, 0, s_side>>>(Wg, Wu, sWg, sWu);
    trans_w2_kernel<<<dim3(H_DIM / 32, I_DIM / 32, 9), 256, 0, s_side>>>(Wd, sWd);
    cudaEventRecord(s_evJoin, s_side);

    // routing chain on main stream (router also writes fp16(x))
    init_kernel<<<1, 32>>>();
    router_kernel<<<T_TOT / 16, 256>>>(X, GW);
    scatter_kernel<<<T_TOT / 256, 256>>>();

    // join
    cudaStreamWaitEvent((cudaStream_t)0, s_evJoin, 0);

    gu_mma_kernel<<<dim3(I_DIM / 64, T_TOT / 128, E_NUM + 1), 256, GU_SMEM>>>(
        wgT, wuT, sgT, suT, inter);
    dn_mma_kernel<<<dim3(H_DIM / 128, T_TOT / 128, E_NUM + 1), 256, DN_SMEM>>>(
        inter, wdT, sdT, dtmp);
    combine_kernel<<<T_TOT / 2, 256>>>(out);
}